// round 5
// baseline (speedup 1.0000x reference)
#include <cuda_runtime.h>
#include <math.h>

#define Nn  32768
#define Cc  512
#define Aa  64
#define CIi 1024
#define QD  576          // C + A
#define EPSf 1e-7f

// ---------------- scratch (device globals; no allocation allowed) ----------------
__device__ float g_q[QD];        // query (raw, then normalized q/||q||)
__device__ float g_erase[Cc];
__device__ float g_t1[Cc];       // Wch@h, later overwritten with cand
__device__ float g_t2[Cc];       // Wci@x
__device__ float g_s1[QD];       // sum_i e_i * full_mem[i,j]
__device__ float g_s2[Cc];       // sum_i e_i^2 * mem[i,c]
__device__ float g_z[Nn];        // pre-softmax logits
__device__ float g_scal[16];     // 1:bp 2:gp 3:ap 4:beta 5:gamma 7:E 8:S
__device__ unsigned g_zkey;      // order-preserving encoded max

__device__ __forceinline__ unsigned encf(float f) {
    unsigned u = __float_as_uint(f);
    return (u & 0x80000000u) ? ~u : (u | 0x80000000u);
}
__device__ __forceinline__ float decf(unsigned k) {
    return __uint_as_float((k & 0x80000000u) ? (k & 0x7FFFFFFFu) : ~k);
}

// ---------------- K0: zero accumulators ----------------
__global__ void k_zero() {
    int t = threadIdx.x;
    for (int j = t; j < QD; j += blockDim.x) g_s1[j] = 0.f;
    for (int j = t; j < Cc; j += blockDim.x) g_s2[j] = 0.f;
    if (t < 16) g_scal[t] = 0.f;
    if (t == 0) g_zkey = 0x00800000u;   // enc(-FLT_MAX)
}

// ---------------- K1: all matvecs + small dots ----------------
// blocks 0..263: 8-row GEMV groups (shared vec read amortized over 8 rows)
//   0..71   W_query (576 rows, len N)  -> g_q     (+ b_query)
//   72..135 W_erase (512 rows, len N)  -> g_erase (+ b_erase)
//   136..199 W_ch   (512 rows, len N)  -> g_t1
//   200..263 W_ci   (512 rows, len CI) -> g_t2
// blocks 264..267: dots u_sharpen.h, u_lru.h, uca[:N].h, uca[N:].x
__global__ __launch_bounds__(256) void k_matvec(
    const float* __restrict__ h,  const float* __restrict__ x,
    const float* __restrict__ Wq, const float* __restrict__ bq,
    const float* __restrict__ We, const float* __restrict__ be,
    const float* __restrict__ Wch, const float* __restrict__ Wci,
    const float* __restrict__ us, const float* __restrict__ ul,
    const float* __restrict__ uca)
{
    int b = blockIdx.x, t = threadIdx.x;
    if (b < 264) {
        const float* W; const float* vec; float* out; const float* bias = nullptr;
        int L, row0;
        if (b < 72)       { W = Wq;  vec = h; out = g_q;     bias = bq; L = Nn;  row0 = b * 8; }
        else if (b < 136) { W = We;  vec = h; out = g_erase; bias = be; L = Nn;  row0 = (b - 72) * 8; }
        else if (b < 200) { W = Wch; vec = h; out = g_t1;               L = Nn;  row0 = (b - 136) * 8; }
        else              { W = Wci; vec = x; out = g_t2;               L = CIi; row0 = (b - 200) * 8; }

        float acc[8];
        #pragma unroll
        for (int r = 0; r < 8; r++) acc[r] = 0.f;

        const float4* v4 = (const float4*)vec;
        int L4 = L >> 2;
        for (int i = t; i < L4; i += 256) {
            float4 hv = v4[i];
            #pragma unroll
            for (int r = 0; r < 8; r++) {
                float4 wv = reinterpret_cast<const float4*>(W + (size_t)(row0 + r) * L)[i];
                acc[r] += wv.x * hv.x + wv.y * hv.y + wv.z * hv.z + wv.w * hv.w;
            }
        }
        #pragma unroll
        for (int r = 0; r < 8; r++)
            for (int o = 16; o; o >>= 1) acc[r] += __shfl_xor_sync(0xffffffffu, acc[r], o);

        __shared__ float sm[8][8];
        int w = t >> 5, lane = t & 31;
        if (lane == 0) {
            #pragma unroll
            for (int r = 0; r < 8; r++) sm[w][r] = acc[r];
        }
        __syncthreads();
        if (t < 8) {
            float v = 0.f;
            #pragma unroll
            for (int w2 = 0; w2 < 8; w2++) v += sm[w2][t];
            int row = row0 + t;
            if (bias) v += bias[row];
            out[row] = v;
        }
    } else {
        int d = b - 264;
        const float* u; const float* vec; int L;
        if (d == 0)      { u = us;       vec = h; L = Nn; }
        else if (d == 1) { u = ul;       vec = h; L = Nn; }
        else if (d == 2) { u = uca;      vec = h; L = Nn; }
        else             { u = uca + Nn; vec = x; L = CIi; }
        float acc = 0.f;
        const float4* u4 = (const float4*)u;
        const float4* v4 = (const float4*)vec;
        for (int i = t; i < (L >> 2); i += 256) {
            float4 a = u4[i], c = v4[i];
            acc += a.x * c.x + a.y * c.y + a.z * c.z + a.w * c.w;
        }
        for (int o = 16; o; o >>= 1) acc += __shfl_xor_sync(0xffffffffu, acc, o);
        __shared__ float sd[8];
        if ((t & 31) == 0) sd[t >> 5] = acc;
        __syncthreads();
        if (t == 0) {
            float tot = 0.f;
            #pragma unroll
            for (int k = 0; k < 8; k++) tot += sd[k];
            if (d == 0) g_scal[1] = tot;
            else if (d == 1) g_scal[2] = tot;
            else atomicAdd(&g_scal[3], tot);
        }
    }
}

// ---------------- K2: finalize scalars, normalize q, compute cand ----------------
__global__ void k_fin1(const float* __restrict__ bsh, const float* __restrict__ blru,
                       const float* __restrict__ bca)
{
    int t = threadIdx.x;              // launched with 576 threads
    __shared__ float red[QD];
    float vq = g_q[t];
    red[t] = vq * vq;
    __syncthreads();
    __shared__ float sc[2];
    if (t == 0) {
        float qs2 = 0.f;
        for (int j = 0; j < QD; j++) qs2 += red[j];
        float qn = fmaxf(sqrtf(qs2), EPSf);
        float bp = g_scal[1] + bsh[0];
        float beta = ((bp > 20.f) ? bp : log1pf(__expf(bp))) + 1.f;
        float gp = g_scal[2] + blru[0];
        float gamma = 1.f / (1.f + __expf(-gp));
        float alpha = g_scal[3] + bca[0];
        g_scal[4] = beta; g_scal[5] = gamma;
        sc[0] = 1.f / qn; sc[1] = alpha;
    }
    __syncthreads();
    g_q[t] *= sc[0];
    if (t < Cc) g_t1[t] = fmaxf(g_t1[t] + sc[1] * g_t2[t], 0.f);   // cand
}

// ---------------- K3: pass 1 over full_mem -> z[i], global max ----------------
__global__ __launch_bounds__(256) void k_pass1(
    const float* __restrict__ Amat, const float* __restrict__ M,
    const float* __restrict__ ema)
{
    __shared__ float qs[QD];
    __shared__ float smax[8];
    int t = threadIdx.x;
    for (int j = t; j < QD; j += 256) qs[j] = g_q[j];
    float beta = g_scal[4], gamma = g_scal[5];
    __syncthreads();

    int w = t >> 5, lane = t & 31;
    int gw = blockIdx.x * 8 + w;      // 8192 warps, 4 rows each
    float lmax = -3.4e38f;
    for (int r = 0; r < 4; r++) {
        int row = gw * 4 + r;
        float2 av = ((const float2*)(Amat + (size_t)row * Aa))[lane];
        float dot = av.x * qs[2 * lane] + av.y * qs[2 * lane + 1];
        float ss  = av.x * av.x + av.y * av.y;
        const float4* c4 = (const float4*)(M + (size_t)row * Cc);
        #pragma unroll
        for (int k = 0; k < 4; k++) {
            float4 v = c4[lane + 32 * k];
            int c0 = Aa + 4 * (lane + 32 * k);
            dot += v.x * qs[c0] + v.y * qs[c0 + 1] + v.z * qs[c0 + 2] + v.w * qs[c0 + 3];
            ss  += v.x * v.x + v.y * v.y + v.z * v.z + v.w * v.w;
        }
        for (int o = 16; o; o >>= 1) {
            dot += __shfl_xor_sync(0xffffffffu, dot, o);
            ss  += __shfl_xor_sync(0xffffffffu, ss, o);
        }
        if (lane == 0) {
            float mn = fmaxf(sqrtf(ss), EPSf);
            float z = beta * (dot / mn) - gamma * ema[row];
            g_z[row] = z;
            lmax = fmaxf(lmax, z);
        }
    }
    if (lane == 0) smax[w] = lmax;
    __syncthreads();
    if (t == 0) {
        float m = smax[0];
        #pragma unroll
        for (int k = 1; k < 8; k++) m = fmaxf(m, smax[k]);
        atomicMax(&g_zkey, encf(m));
    }
}

// ---------------- K4: pass 2 -> s1, s2, E, S (unnormalized) ----------------
__global__ __launch_bounds__(256) void k_pass2(
    const float* __restrict__ Amat, const float* __restrict__ M)
{
    __shared__ float s1sh[QD];
    __shared__ float s2sh[Cc];
    __shared__ float es[2];
    int t = threadIdx.x;
    for (int j = t; j < QD; j += 256) s1sh[j] = 0.f;
    for (int j = t; j < Cc; j += 256) s2sh[j] = 0.f;
    if (t == 0) { es[0] = 0.f; es[1] = 0.f; }
    float zmax = decf(g_zkey);
    __syncthreads();

    int w = t >> 5, lane = t & 31;
    int gw = blockIdx.x * 8 + w;      // 4096 warps, 8 rows each
    float a1x = 0.f, a1y = 0.f;
    float4 c1[4], c2[4];
    #pragma unroll
    for (int k = 0; k < 4; k++) {
        c1[k] = make_float4(0.f, 0.f, 0.f, 0.f);
        c2[k] = make_float4(0.f, 0.f, 0.f, 0.f);
    }
    float eacc = 0.f, sacc = 0.f;

    for (int r = 0; r < 8; r++) {
        int row = gw * 8 + r;
        float e = __expf(g_z[row] - zmax);
        float e2 = e * e;
        float2 av = ((const float2*)(Amat + (size_t)row * Aa))[lane];
        a1x += e * av.x; a1y += e * av.y;
        const float4* c4 = (const float4*)(M + (size_t)row * Cc);
        #pragma unroll
        for (int k = 0; k < 4; k++) {
            float4 v = c4[lane + 32 * k];
            c1[k].x += e * v.x;  c1[k].y += e * v.y;  c1[k].z += e * v.z;  c1[k].w += e * v.w;
            c2[k].x += e2 * v.x; c2[k].y += e2 * v.y; c2[k].z += e2 * v.z; c2[k].w += e2 * v.w;
        }
        if (lane == 0) { eacc += e; sacc += e2; }
    }

    atomicAdd(&s1sh[2 * lane],     a1x);
    atomicAdd(&s1sh[2 * lane + 1], a1y);
    #pragma unroll
    for (int k = 0; k < 4; k++) {
        int base = 4 * (lane + 32 * k);
        atomicAdd(&s1sh[Aa + base + 0], c1[k].x);
        atomicAdd(&s1sh[Aa + base + 1], c1[k].y);
        atomicAdd(&s1sh[Aa + base + 2], c1[k].z);
        atomicAdd(&s1sh[Aa + base + 3], c1[k].w);
        atomicAdd(&s2sh[base + 0], c2[k].x);
        atomicAdd(&s2sh[base + 1], c2[k].y);
        atomicAdd(&s2sh[base + 2], c2[k].z);
        atomicAdd(&s2sh[base + 3], c2[k].w);
    }
    if (lane == 0) { atomicAdd(&es[0], eacc); atomicAdd(&es[1], sacc); }
    __syncthreads();

    for (int j = t; j < QD; j += 256) atomicAdd(&g_s1[j], s1sh[j]);
    for (int j = t; j < Cc; j += 256) atomicAdd(&g_s2[j], s2sh[j]);
    if (t == 0) { atomicAdd(&g_scal[7], es[0]); atomicAdd(&g_scal[8], es[1]); }
}

// ---------------- K5: combine to output ----------------
__global__ void k_fin2(float* __restrict__ out) {
    int t = threadIdx.x;              // 576 threads
    float E = g_scal[7];
    float invE = 1.f / E;
    float inv2 = invE * invE;
    float S = g_scal[8];
    if (t < Aa) {
        out[t] = g_s1[t] * invE;
    } else if (t < QD) {
        int c = t - Aa;
        out[t] = g_s1[t] * invE - g_erase[c] * (g_s2[c] * inv2) + g_t1[c] * (S * inv2);
    }
}

extern "C" void kernel_launch(void* const* d_in, const int* in_sizes, int n_in,
                              void* d_out, int out_size)
{
    const float* h    = (const float*)d_in[0];
    const float* x    = (const float*)d_in[1];
    const float* mem  = (const float*)d_in[2];
    const float* amat = (const float*)d_in[3];
    const float* ema  = (const float*)d_in[4];
    const float* Wq   = (const float*)d_in[5];
    const float* bq   = (const float*)d_in[6];
    const float* us   = (const float*)d_in[7];
    const float* bsh  = (const float*)d_in[8];
    const float* ul   = (const float*)d_in[9];
    const float* blru = (const float*)d_in[10];
    const float* We   = (const float*)d_in[11];
    const float* be   = (const float*)d_in[12];
    const float* Wch  = (const float*)d_in[13];
    const float* Wci  = (const float*)d_in[14];
    const float* uca  = (const float*)d_in[15];
    const float* bca  = (const float*)d_in[16];

    k_zero<<<1, 256>>>();
    k_matvec<<<268, 256>>>(h, x, Wq, bq, We, be, Wch, Wci, us, ul, uca);
    k_fin1<<<1, QD>>>(bsh, blru, bca);
    k_pass1<<<1024, 256>>>(amat, mem, ema);
    k_pass2<<<512, 256>>>(amat, mem);
    k_fin2<<<1, QD>>>((float*)d_out);
}

// round 7
// speedup vs baseline: 1.1199x; 1.1199x over previous
#include <cuda_runtime.h>
#include <math.h>

#define Nn  32768
#define Cc  512
#define Aa  64
#define CIi 1024
#define QD  576          // C + A
#define EPSf 1e-7f

// ---------------- scratch: ONE contiguous struct so a single memset zeroes it ----
struct Acc {
    float q[QD];      // W_query@h partials (bias added later)
    float er[Cc];     // W_erase@h partials
    float t1[Cc];     // Wch@h partials
    float t2[Cc];     // Wci@x partials
    float s1[QD];     // sum_i e_i * full_mem[i,j]
    float s2[Cc];     // sum_i e_i^2 * mem[i,c]
    float scal[16];   // 1:us.h 2:ul.h 3:uca[:N].h 6:uca[N:].x 7:E 8:S
    unsigned zkey;    // order-preserving encoded max; 0 == -inf sentinel
};
__device__ Acc g;
__device__ float g_z[Nn];

__device__ __forceinline__ unsigned encf(float f) {
    unsigned u = __float_as_uint(f);
    return (u & 0x80000000u) ? ~u : (u | 0x80000000u);
}
__device__ __forceinline__ float decf(unsigned k) {
    return __uint_as_float((k & 0x80000000u) ? (k & 0x7FFFFFFFu) : ~k);
}

// ---------------- K1: all matvecs + small dots (column-chunked, 868 blocks) ------
//  b <  288 : W_query (72 groups x 4 chunks)  -> g.q
//  b <  544 : W_erase (64 groups x 4 chunks)  -> g.er
//  b <  800 : W_ch    (64 groups x 4 chunks)  -> g.t1
//  b <  864 : W_ci    (64 groups x 1 chunk)   -> g.t2
//  b <  868 : dots us.h, ul.h, uca[:N].h, uca[N:].x -> g.scal slots
__global__ __launch_bounds__(256) void k_matvec(
    const float* __restrict__ h,  const float* __restrict__ x,
    const float* __restrict__ Wq, const float* __restrict__ We,
    const float* __restrict__ Wch, const float* __restrict__ Wci,
    const float* __restrict__ us, const float* __restrict__ ul,
    const float* __restrict__ uca)
{
    int b = blockIdx.x, t = threadIdx.x;
    int w = t >> 5, lane = t & 31;

    if (b < 800) {
        const float* W; float* out; int row0, chunk;
        if (b < 288)      { W = Wq;  out = g.q;  row0 = (b >> 2) * 8;        chunk = b & 3; }
        else if (b < 544) { int bb = b - 288; W = We;  out = g.er; row0 = (bb >> 2) * 8; chunk = bb & 3; }
        else              { int bb = b - 544; W = Wch; out = g.t1; row0 = (bb >> 2) * 8; chunk = bb & 3; }

        const float4* v4 = (const float4*)h + chunk * 2048;
        const size_t cbase = (size_t)chunk * 8192;

        float acc[8];
        #pragma unroll
        for (int r = 0; r < 8; r++) acc[r] = 0.f;

        #pragma unroll 2
        for (int i = t; i < 2048; i += 256) {
            float4 hv = v4[i];
            #pragma unroll
            for (int r = 0; r < 8; r++) {
                float4 wv = reinterpret_cast<const float4*>(W + (size_t)(row0 + r) * Nn + cbase)[i];
                acc[r] += wv.x * hv.x + wv.y * hv.y + wv.z * hv.z + wv.w * hv.w;
            }
        }
        #pragma unroll
        for (int r = 0; r < 8; r++)
            for (int o = 16; o; o >>= 1) acc[r] += __shfl_xor_sync(0xffffffffu, acc[r], o);

        __shared__ float sm[8][8];
        if (lane == 0) {
            #pragma unroll
            for (int r = 0; r < 8; r++) sm[w][r] = acc[r];
        }
        __syncthreads();
        if (t < 8) {
            float v = 0.f;
            #pragma unroll
            for (int w2 = 0; w2 < 8; w2++) v += sm[w2][t];
            atomicAdd(&out[row0 + t], v);
        }
    } else if (b < 864) {
        // W_ci: 8 rows x 1024, one block per group (exclusive rows -> plain store)
        int row0 = (b - 800) * 8;
        const float4* v4 = (const float4*)x;
        float acc[8];
        #pragma unroll
        for (int r = 0; r < 8; r++) acc[r] = 0.f;
        {
            int i = t;   // 1024/4 = 256 float4 -> exactly one per thread
            float4 hv = v4[i];
            #pragma unroll
            for (int r = 0; r < 8; r++) {
                float4 wv = reinterpret_cast<const float4*>(Wci + (size_t)(row0 + r) * CIi)[i];
                acc[r] += wv.x * hv.x + wv.y * hv.y + wv.z * hv.z + wv.w * hv.w;
            }
        }
        #pragma unroll
        for (int r = 0; r < 8; r++)
            for (int o = 16; o; o >>= 1) acc[r] += __shfl_xor_sync(0xffffffffu, acc[r], o);
        __shared__ float sm2[8][8];
        if (lane == 0) {
            #pragma unroll
            for (int r = 0; r < 8; r++) sm2[w][r] = acc[r];
        }
        __syncthreads();
        if (t < 8) {
            float v = 0.f;
            #pragma unroll
            for (int w2 = 0; w2 < 8; w2++) v += sm2[w2][t];
            g.t2[row0 + t] = v;
        }
    } else {
        int d = b - 864;
        const float* u; const float* vec; int L; int slot;
        if (d == 0)      { u = us;       vec = h; L = Nn;  slot = 1; }
        else if (d == 1) { u = ul;       vec = h; L = Nn;  slot = 2; }
        else if (d == 2) { u = uca;      vec = h; L = Nn;  slot = 3; }
        else             { u = uca + Nn; vec = x; L = CIi; slot = 6; }
        float acc = 0.f;
        const float4* u4 = (const float4*)u;
        const float4* v4 = (const float4*)vec;
        for (int i = t; i < (L >> 2); i += 256) {
            float4 a = u4[i], c = v4[i];
            acc += a.x * c.x + a.y * c.y + a.z * c.z + a.w * c.w;
        }
        for (int o = 16; o; o >>= 1) acc += __shfl_xor_sync(0xffffffffu, acc, o);
        __shared__ float sd[8];
        if (lane == 0) sd[w] = acc;
        __syncthreads();
        if (t == 0) {
            float tot = 0.f;
            #pragma unroll
            for (int k = 0; k < 8; k++) tot += sd[k];
            g.scal[slot] = tot;
        }
    }
}

// ---------------- K2: pass 1 over full_mem -> z[i], global max -------------------
// Scalar finalization (beta, gamma, ||q||) recomputed redundantly per block
// (~600 L2-hit loads, cheap) to kill the 1-block fin kernel.
__global__ __launch_bounds__(256) void k_pass1(
    const float* __restrict__ Amat, const float* __restrict__ M,
    const float* __restrict__ ema, const float* __restrict__ bq,
    const float* __restrict__ bsh, const float* __restrict__ blru)
{
    __shared__ float qs[QD];
    __shared__ float red[8];
    __shared__ float sc[2];
    int t = threadIdx.x, w = t >> 5, lane = t & 31;

    float p = 0.f;
    for (int j = t; j < QD; j += 256) {
        float v = g.q[j] + bq[j];
        qs[j] = v;
        p += v * v;
    }
    for (int o = 16; o; o >>= 1) p += __shfl_xor_sync(0xffffffffu, p, o);
    if (lane == 0) red[w] = p;
    __syncthreads();
    if (t == 0) {
        float qs2 = 0.f;
        #pragma unroll
        for (int k = 0; k < 8; k++) qs2 += red[k];
        float qn = fmaxf(sqrtf(qs2), EPSf);
        float bp = g.scal[1] + bsh[0];
        float beta = ((bp > 20.f) ? bp : log1pf(__expf(bp))) + 1.f;
        float gp = g.scal[2] + blru[0];
        sc[0] = beta / qn;                       // fold 1/||q|| into beta
        sc[1] = 1.f / (1.f + __expf(-gp));       // gamma
    }
    __syncthreads();
    float betap = sc[0], gamma = sc[1];

    int gw = blockIdx.x * 8 + w;                 // 8192 warps, 4 rows each
    float lmax = -3.4e38f;
    #pragma unroll
    for (int rr = 0; rr < 4; rr += 2) {          // 2-row interleave: 2x MLP,
        int row0 = gw * 4 + rr;                  // overlapped reduction chains
        float2 av0 = ((const float2*)(Amat + (size_t)row0 * Aa))[lane];
        float2 av1 = ((const float2*)(Amat + (size_t)(row0 + 1) * Aa))[lane];
        float q0a = qs[2 * lane], q1a = qs[2 * lane + 1];
        float d0 = av0.x * q0a + av0.y * q1a;
        float s0 = av0.x * av0.x + av0.y * av0.y;
        float d1 = av1.x * q0a + av1.y * q1a;
        float s1 = av1.x * av1.x + av1.y * av1.y;
        const float4* c0 = (const float4*)(M + (size_t)row0 * Cc);
        const float4* c1 = (const float4*)(M + (size_t)(row0 + 1) * Cc);
        #pragma unroll
        for (int k = 0; k < 4; k++) {
            int idx = lane + 32 * k;
            float4 v0 = c0[idx];
            float4 v1 = c1[idx];
            int cb = Aa + 4 * idx;
            float qa = qs[cb], qb = qs[cb + 1], qc = qs[cb + 2], qd = qs[cb + 3];
            d0 += v0.x * qa + v0.y * qb + v0.z * qc + v0.w * qd;
            s0 += v0.x * v0.x + v0.y * v0.y + v0.z * v0.z + v0.w * v0.w;
            d1 += v1.x * qa + v1.y * qb + v1.z * qc + v1.w * qd;
            s1 += v1.x * v1.x + v1.y * v1.y + v1.z * v1.z + v1.w * v1.w;
        }
        #pragma unroll
        for (int o = 16; o; o >>= 1) {
            d0 += __shfl_xor_sync(0xffffffffu, d0, o);
            d1 += __shfl_xor_sync(0xffffffffu, d1, o);
            s0 += __shfl_xor_sync(0xffffffffu, s0, o);
            s1 += __shfl_xor_sync(0xffffffffu, s1, o);
        }
        if (lane == 0) {
            float z0 = betap * d0 / fmaxf(sqrtf(s0), EPSf) - gamma * ema[row0];
            float z1 = betap * d1 / fmaxf(sqrtf(s1), EPSf) - gamma * ema[row0 + 1];
            g_z[row0] = z0;
            g_z[row0 + 1] = z1;
            lmax = fmaxf(lmax, fmaxf(z0, z1));
        }
    }
    if (lane == 0) red[w] = lmax;
    __syncthreads();
    if (t == 0) {
        float m = red[0];
        #pragma unroll
        for (int k = 1; k < 8; k++) m = fmaxf(m, red[k]);
        atomicMax(&g.zkey, encf(m));
    }
}

// ---------------- K3: pass 2 -> s1, s2, E, S (unnormalized) ----------------------
__global__ __launch_bounds__(256) void k_pass2(
    const float* __restrict__ Amat, const float* __restrict__ M)
{
    __shared__ float s1sh[QD];
    __shared__ float s2sh[Cc];
    __shared__ float es[2];
    int t = threadIdx.x;
    for (int j = t; j < QD; j += 256) s1sh[j] = 0.f;
    for (int j = t; j < Cc; j += 256) s2sh[j] = 0.f;
    if (t == 0) { es[0] = 0.f; es[1] = 0.f; }
    float zmax = decf(g.zkey);
    __syncthreads();

    int w = t >> 5, lane = t & 31;
    int gw = blockIdx.x * 8 + w;                 // 4096 warps, 8 rows each
    float a1x = 0.f, a1y = 0.f;
    float4 c1[4], c2[4];
    #pragma unroll
    for (int k = 0; k < 4; k++) {
        c1[k] = make_float4(0.f, 0.f, 0.f, 0.f);
        c2[k] = make_float4(0.f, 0.f, 0.f, 0.f);
    }
    float eacc = 0.f, sacc = 0.f;

    for (int r = 0; r < 8; r++) {
        int row = gw * 8 + r;
        float e = __expf(g_z[row] - zmax);
        float e2 = e * e;
        float2 av = ((const float2*)(Amat + (size_t)row * Aa))[lane];
        a1x += e * av.x; a1y += e * av.y;
        const float4* c4 = (const float4*)(M + (size_t)row * Cc);
        #pragma unroll
        for (int k = 0; k < 4; k++) {
            float4 v = c4[lane + 32 * k];
            c1[k].x += e * v.x;  c1[k].y += e * v.y;  c1[k].z += e * v.z;  c1[k].w += e * v.w;
            c2[k].x += e2 * v.x; c2[k].y += e2 * v.y; c2[k].z += e2 * v.z; c2[k].w += e2 * v.w;
        }
        if (lane == 0) { eacc += e; sacc += e2; }
    }

    atomicAdd(&s1sh[2 * lane],     a1x);
    atomicAdd(&s1sh[2 * lane + 1], a1y);
    #pragma unroll
    for (int k = 0; k < 4; k++) {
        int base = 4 * (lane + 32 * k);
        atomicAdd(&s1sh[Aa + base + 0], c1[k].x);
        atomicAdd(&s1sh[Aa + base + 1], c1[k].y);
        atomicAdd(&s1sh[Aa + base + 2], c1[k].z);
        atomicAdd(&s1sh[Aa + base + 3], c1[k].w);
        atomicAdd(&s2sh[base + 0], c2[k].x);
        atomicAdd(&s2sh[base + 1], c2[k].y);
        atomicAdd(&s2sh[base + 2], c2[k].z);
        atomicAdd(&s2sh[base + 3], c2[k].w);
    }
    if (lane == 0) { atomicAdd(&es[0], eacc); atomicAdd(&es[1], sacc); }
    __syncthreads();

    for (int j = t; j < QD; j += 256) atomicAdd(&g.s1[j], s1sh[j]);
    for (int j = t; j < Cc; j += 256) atomicAdd(&g.s2[j], s2sh[j]);
    if (t == 0) { atomicAdd(&g.scal[7], es[0]); atomicAdd(&g.scal[8], es[1]); }
}

// ---------------- K4: combine to output (cand + biases folded in) ---------------
__global__ void k_fin2(const float* __restrict__ be, const float* __restrict__ bca,
                       float* __restrict__ out)
{
    int t = threadIdx.x;              // 576 threads
    float E = g.scal[7];
    float S = g.scal[8];
    float invE = 1.f / E;
    float inv2 = invE * invE;
    if (t < Aa) {
        out[t] = g.s1[t] * invE;
    } else {
        int c = t - Aa;
        float alpha = g.scal[3] + g.scal[6] + bca[0];
        float cand  = fmaxf(g.t1[c] + alpha * g.t2[c], 0.f);
        float er    = g.er[c] + be[c];
        out[t] = g.s1[t] * invE - er * (g.s2[c] * inv2) + cand * (S * inv2);
    }
}

extern "C" void kernel_launch(void* const* d_in, const int* in_sizes, int n_in,
                              void* d_out, int out_size)
{
    const float* h    = (const float*)d_in[0];
    const float* x    = (const float*)d_in[1];
    const float* mem  = (const float*)d_in[2];
    const float* amat = (const float*)d_in[3];
    const float* ema  = (const float*)d_in[4];
    const float* Wq   = (const float*)d_in[5];
    const float* bq   = (const float*)d_in[6];
    const float* us   = (const float*)d_in[7];
    const float* bsh  = (const float*)d_in[8];
    const float* ul   = (const float*)d_in[9];
    const float* blru = (const float*)d_in[10];
    const float* We   = (const float*)d_in[11];
    const float* be   = (const float*)d_in[12];
    const float* Wch  = (const float*)d_in[13];
    const float* Wci  = (const float*)d_in[14];
    const float* uca  = (const float*)d_in[15];
    const float* bca  = (const float*)d_in[16];

    void* accp = nullptr;
    cudaGetSymbolAddress(&accp, g);
    cudaMemsetAsync(accp, 0, sizeof(Acc));   // zeroes all accumulators + zkey(-inf)

    k_matvec<<<868, 256>>>(h, x, Wq, We, Wch, Wci, us, ul, uca);
    k_pass1<<<1024, 256>>>(amat, mem, ema, bq, bsh, blru);
    k_pass2<<<512, 256>>>(amat, mem);
    k_fin2<<<1, QD>>>(be, bca, (float*)d_out);
}